// round 15
// baseline (speedup 1.0000x reference)
#include <cuda_runtime.h>
#include <cuda_fp16.h>
#include <stdint.h>
#include <math.h>

#define B_ 2
#define T_ 2048
#define C_ 1024
#define H_ 16
#define D_ 64
#define M_ (B_*T_)   // 4096 rows

// Scratch (allocation-free).
__device__ __half g_qh[M_*C_];     // Q, pre-scaled by 0.125*log2e
__device__ __half g_kh[M_*C_];
__device__ __half g_vh[M_*C_];
__device__ __half g_oh[M_*C_];     // attention out
__device__ __half g_xh[M_*C_];     // x rounded to fp16
__device__ __half g_wh[4*C_*C_];   // W^T rounded to fp16: [sel][n][k]

__device__ __forceinline__ float ex2f(float x) {
    float y;
    asm("ex2.approx.ftz.f32 %0, %1;" : "=f"(y) : "f"(x));
    return y;
}

__device__ __forceinline__ void mma_f16(float c[4],
    uint32_t a0, uint32_t a1, uint32_t a2, uint32_t a3,
    uint32_t b0, uint32_t b1)
{
    asm volatile(
        "mma.sync.aligned.m16n8k16.row.col.f32.f16.f16.f32 "
        "{%0,%1,%2,%3},{%4,%5,%6,%7},{%8,%9},{%0,%1,%2,%3};"
        : "+f"(c[0]), "+f"(c[1]), "+f"(c[2]), "+f"(c[3])
        : "r"(a0), "r"(a1), "r"(a2), "r"(a3), "r"(b0), "r"(b1));
}

__device__ __forceinline__ void ldsm4(uint32_t r[4], uint32_t saddr) {
    asm volatile("ldmatrix.sync.aligned.m8n8.x4.shared.b16 {%0,%1,%2,%3}, [%4];"
        : "=r"(r[0]), "=r"(r[1]), "=r"(r[2]), "=r"(r[3]) : "r"(saddr));
}

__device__ __forceinline__ void ldsm4t(uint32_t r[4], uint32_t saddr) {
    asm volatile("ldmatrix.sync.aligned.m8n8.x4.trans.shared.b16 {%0,%1,%2,%3}, [%4];"
        : "=r"(r[0]), "=r"(r[1]), "=r"(r[2]), "=r"(r[3]) : "r"(saddr));
}

__device__ __forceinline__ void cpa16(void* dst, const void* src) {
    uint32_t d = (uint32_t)__cvta_generic_to_shared(dst);
    asm volatile("cp.async.cg.shared.global [%0], [%1], 16;" :: "r"(d), "l"(src));
}
#define CP_COMMIT() asm volatile("cp.async.commit_group;")
#define CP_WAIT(N)  asm volatile("cp.async.wait_group %0;" :: "n"(N))

__device__ __forceinline__ uint32_t pack_h2(float a, float b) {
    __half2 h = __floats2half2_rn(a, b);
    return *(uint32_t*)&h;
}

// ---------------------------------------------------------------------------
// Fused conversion: blocks [0,1024) x fp32->fp16; [1024,2048) W round+transpose.
// ---------------------------------------------------------------------------
__global__ __launch_bounds__(256) void conv_all_kernel(
    const float* __restrict__ x,
    const float* __restrict__ Wq, const float* __restrict__ Wk,
    const float* __restrict__ Wv, const float* __restrict__ Wo)
{
    __shared__ __half tile[64][68];
    if (blockIdx.x < 1024) {
        #pragma unroll
        for (int l = 0; l < 4; l++) {
            int i4 = blockIdx.x * 1024 + l * 256 + threadIdx.x;
            float4 v = *(const float4*)&x[(size_t)i4 << 2];
            uint2 u = { pack_h2(v.x, v.y), pack_h2(v.z, v.w) };
            *(uint2*)&g_xh[(size_t)i4 << 2] = u;
        }
        return;
    }
    const float* Ws[4] = { Wq, Wk, Wv, Wo };
    int bx  = blockIdx.x - 1024;
    int mat = bx >> 8;
    int t   = bx & 255;
    int kb  = (t >> 4) << 6;
    int nb  = (t & 15) << 6;
    const float* W = Ws[mat];
    int tid = threadIdx.x;
    int rr = tid >> 4, c4 = (tid & 15) << 2;
    #pragma unroll
    for (int l = 0; l < 4; l++) {
        int row = rr + l * 16;
        float4 v = *(const float4*)&W[(size_t)(kb + row) * C_ + nb + c4];
        tile[row][c4 + 0] = __float2half_rn(v.x);
        tile[row][c4 + 1] = __float2half_rn(v.y);
        tile[row][c4 + 2] = __float2half_rn(v.z);
        tile[row][c4 + 3] = __float2half_rn(v.w);
    }
    __syncthreads();
    __half* dst = g_wh + ((size_t)mat << 20);
    #pragma unroll
    for (int l = 0; l < 4; l++) {
        int row = rr + l * 16;
        __half2 p0 = __halves2half2(tile[c4 + 0][row], tile[c4 + 1][row]);
        __half2 p1 = __halves2half2(tile[c4 + 2][row], tile[c4 + 3][row]);
        uint2 u = { *(uint32_t*)&p0, *(uint32_t*)&p1 };
        *(uint2*)&dst[(size_t)(nb + row) * C_ + kb + c4] = u;
    }
}

// ---------------------------------------------------------------------------
// FP16 GEMM (m16n8k16): R13 configuration (proven best).
// A [m][k] half, Wt [n][k] half. 128x128 tile, BK=64, 3-stage cp.async,
// 256 thr (8 warps 2x4), warp 64x32. ldmatrix fragments. SAH=72 pad.
// ---------------------------------------------------------------------------
#define SAH 72
#define STG_H (256*SAH)             // 18432 halves per stage
#define GEMM_SMEM (3*STG_H*2)       // 110592 bytes

__device__ __forceinline__ void gemm_issue(
    __half* stage, const __half* A, const __half* Wt,
    int brow, int bcol, int k0, int tid)
{
    __half* As = stage;
    __half* Ws = stage + 128 * SAH;
    #pragma unroll
    for (int l = 0; l < 8; l++) {
        int idx = tid + (l << 8);
        int row = idx >> 3;
        int c16 = (idx & 7) << 3;
        if (row < 128)
            cpa16(&As[row * SAH + c16], &A[(size_t)(brow + row) * C_ + k0 + c16]);
        else
            cpa16(&Ws[(row - 128) * SAH + c16],
                  &Wt[(size_t)(bcol + row - 128) * C_ + k0 + c16]);
    }
}

__device__ __forceinline__ void gemm_pipe(
    const __half* __restrict__ A, const __half* __restrict__ Wt,
    const float* __restrict__ bias, void* __restrict__ Cm,
    int brow, int bcol, int outHalf, float sc)
{
    extern __shared__ __half smh[];
    const int tid  = threadIdx.x;
    const int lane = tid & 31;
    const int warp = tid >> 5;
    const int wr   = warp >> 2;
    const int wc   = warp & 3;
    const int lg   = lane >> 2;
    const int lt   = lane & 3;

    const int arow = lane & 15;
    const int ah8  = ((lane >> 4) & 1) * 8;
    const int brw  = ((lane >> 4) & 1) * 8 + (lane & 7);
    const int bh8  = ((lane >> 3) & 1) * 8;
    const uint32_t smem_u32 = (uint32_t)__cvta_generic_to_shared(smh);

    float acc[4][4][4];
    #pragma unroll
    for (int mf = 0; mf < 4; mf++)
        #pragma unroll
        for (int nf = 0; nf < 4; nf++)
            #pragma unroll
            for (int r = 0; r < 4; r++) acc[mf][nf][r] = 0.f;

    gemm_issue(smh,         A, Wt, brow, bcol, 0,  tid); CP_COMMIT();
    gemm_issue(smh + STG_H, A, Wt, brow, bcol, 64, tid); CP_COMMIT();

    const int NIT = C_ / 64;   // 16
    #pragma unroll 1
    for (int it = 0; it < NIT; it++) {
        CP_WAIT(1);
        __syncthreads();
        int kn = (it + 2) * 64;
        if (kn < C_) gemm_issue(smh + ((it + 2) % 3) * STG_H, A, Wt, brow, bcol, kn, tid);
        CP_COMMIT();

        uint32_t sbase = smem_u32 + (uint32_t)((it % 3) * STG_H) * 2u;
        uint32_t aaddr = sbase + (uint32_t)((wr * 64 + arow) * SAH + ah8) * 2u;
        uint32_t baddr = sbase + (uint32_t)(128 * SAH) * 2u
                       + (uint32_t)((wc * 32 + brw) * SAH + bh8) * 2u;

        #pragma unroll
        for (int ks = 0; ks < 4; ks++) {
            const int kb = ks * 16;
            uint32_t b0[4], b1[4];
            ldsm4(b0, baddr + (uint32_t)kb * 2u);
            ldsm4(b1, baddr + (uint32_t)(16 * SAH + kb) * 2u);
            #pragma unroll
            for (int mf = 0; mf < 4; mf++) {
                uint32_t a[4];
                ldsm4(a, aaddr + (uint32_t)(mf * 16 * SAH + kb) * 2u);
                mma_f16(acc[mf][0], a[0], a[1], a[2], a[3], b0[0], b0[1]);
                mma_f16(acc[mf][1], a[0], a[1], a[2], a[3], b0[2], b0[3]);
                mma_f16(acc[mf][2], a[0], a[1], a[2], a[3], b1[0], b1[1]);
                mma_f16(acc[mf][3], a[0], a[1], a[2], a[3], b1[2], b1[3]);
            }
        }
    }

    #pragma unroll
    for (int mf = 0; mf < 4; mf++) {
        int row0 = brow + wr * 64 + mf * 16 + lg;
        #pragma unroll
        for (int nf = 0; nf < 4; nf++) {
            int col = bcol + wc * 32 + nf * 8 + lt * 2;
            float bx = bias[col], by = bias[col + 1];
            float v00 = (acc[mf][nf][0] + bx) * sc, v01 = (acc[mf][nf][1] + by) * sc;
            float v10 = (acc[mf][nf][2] + bx) * sc, v11 = (acc[mf][nf][3] + by) * sc;
            if (outHalf) {
                __half* Ch = (__half*)Cm;
                uint32_t o0 = pack_h2(v00, v01), o1 = pack_h2(v10, v11);
                *(uint32_t*)&Ch[(size_t)row0 * C_ + col]       = o0;
                *(uint32_t*)&Ch[(size_t)(row0 + 8) * C_ + col] = o1;
            } else {
                float* Cf = (float*)Cm;
                float2 o0 = { v00, v01 };
                float2 o1 = { v10, v11 };
                *(float2*)&Cf[(size_t)row0 * C_ + col]       = o0;
                *(float2*)&Cf[(size_t)(row0 + 8) * C_ + col] = o1;
            }
        }
    }
}

__global__ __launch_bounds__(256) void qkv_gemm_kernel(
    const float* __restrict__ bq, const float* __restrict__ bk,
    const float* __restrict__ bv)
{
    int sel  = blockIdx.x >> 3;
    int bcol = (blockIdx.x & 7) * 128;
    int brow = blockIdx.y * 128;
    const __half* Wt  = g_wh + ((size_t)sel << 20);
    const float* bias = (sel == 0) ? bq : (sel == 1) ? bk : bv;
    __half* Cm        = (sel == 0) ? g_qh : (sel == 1) ? g_kh : g_vh;
    float sc = (sel == 0) ? 0.125f * 1.4426950408889634f : 1.0f;
    gemm_pipe(g_xh, Wt, bias, Cm, brow, bcol, 1, sc);
}

__global__ __launch_bounds__(256) void out_gemm_kernel(
    const float* __restrict__ bo, float* __restrict__ out)
{
    gemm_pipe(g_oh, g_wh + ((size_t)3 << 20), bo, out,
              blockIdx.y * 128, blockIdx.x * 128, 0, 1.0f);
}

// ---------------------------------------------------------------------------
// FP16 flash attention (m16n8k16), ALiBi + causal.
// NEW: CTA = 128 queries, 256 thr (8 warps x 16 rows). KV tiles shared by
// 8 warps (halved L1 traffic); fully-masked diagonal tiles skipped per-warp.
// SMEM: 2 KV stages (36KB) + P 16KB = 52KB -> 2 CTA/SM. 512 CTAs.
// ---------------------------------------------------------------------------
#define SKH 72
#define AST_H (128*SKH)                   // 9216 halves per KV stage
#define PS_OFFH (2*AST_H)                 // P region offset in halves
#define ATT_SMEM ((2*AST_H + 128*64)*2)   // 53248 bytes

__device__ __forceinline__ void attn_issue_kv(
    __half* stage, int b, int h, int k0, int tid)
{
    __half* Ks = stage;
    __half* Vs = stage + 64 * SKH;
    #pragma unroll
    for (int l = 0; l < 4; l++) {
        int idx = tid + (l << 8);
        int row = idx >> 3;
        int c16 = (idx & 7) << 3;
        if (row < 64)
            cpa16(&Ks[row * SKH + c16],
                  &g_kh[(size_t)(b * T_ + k0 + row) * C_ + h * D_ + c16]);
        else
            cpa16(&Vs[(row - 64) * SKH + c16],
                  &g_vh[(size_t)(b * T_ + k0 + row - 64) * C_ + h * D_ + c16]);
    }
}

__global__ __launch_bounds__(256) void attn_mma_kernel()
{
    extern __shared__ __half smh[];

    const int tid  = threadIdx.x;
    const int lane = tid & 31;
    const int warp = tid >> 5;
    const int lg   = lane >> 2;
    const int lt   = lane & 3;
    const int h    = blockIdx.y;
    const int b    = blockIdx.z;
    const int qbase = (gridDim.x - 1 - blockIdx.x) * 128;   // heavy-first

    const float slope = exp2f(-0.5f * (float)(h + 1)) * 1.4426950408889634f;

    const int arow = lane & 15;
    const int ah8  = ((lane >> 4) & 1) * 8;
    const int brw  = ((lane >> 4) & 1) * 8 + (lane & 7);
    const int bh8  = ((lane >> 3) & 1) * 8;
    const uint32_t sm_u32 = (uint32_t)__cvta_generic_to_shared(smh);

    const int wmin = qbase + warp * 16;
    const int r0 = wmin + lg;

    // Q fragments (Q pre-scaled by 0.125*log2e at projection time).
    uint32_t qf[4][4];
    {
        const __half* q0 = &g_qh[(size_t)(b * T_ + r0) * C_ + h * D_];
        const __half* q1 = q0 + 8 * C_;
        #pragma unroll
        for (int ks = 0; ks < 4; ks++) {
            int c = ks * 16 + 2 * lt;
            qf[ks][0] = *(const uint32_t*)&q0[c];
            qf[ks][1] = *(const uint32_t*)&q1[c];
            qf[ks][2] = *(const uint32_t*)&q0[c + 8];
            qf[ks][3] = *(const uint32_t*)&q1[c + 8];
        }
    }

    float oacc[8][4];
    #pragma unroll
    for (int nf = 0; nf < 8; nf++)
        #pragma unroll
        for (int r = 0; r < 4; r++) oacc[nf][r] = 0.f;
    float m0 = -1e30f, m1 = -1e30f;
    float lp0 = 0.f, lp1 = 0.f;     // per-thread partial row sums (deferred)

    const int ntiles = qbase / 64 + 2;   // horizon = qbase + 128 queries
    __half* Pw = smh + PS_OFFH + warp * 16 * 64;
    const uint32_t pw_u32 = sm_u32 + (uint32_t)(PS_OFFH + warp * 16 * 64) * 2u;

    attn_issue_kv(smh, b, h, 0, tid); CP_COMMIT();

    #pragma unroll 1
    for (int t = 0; t < ntiles; t++) {
        CP_WAIT(0);
        __syncthreads();
        if (t + 1 < ntiles)
            attn_issue_kv(smh + ((t + 1) & 1) * AST_H, b, h, (t + 1) * 64, tid);
        CP_COMMIT();

        const int k0 = t * 64;
        if (k0 > wmin + 15) continue;   // tile fully masked for this warp

        const uint32_t st_u32 = sm_u32 + (uint32_t)((t & 1) * AST_H) * 2u;
        const uint32_t kaddr  = st_u32 + (uint32_t)(brw * SKH + bh8) * 2u;
        const uint32_t vaddr  = st_u32 + (uint32_t)(64 * SKH) * 2u
                              + (uint32_t)(arow * SKH + ah8) * 2u;

        // S = Q K^T  (16 x 64)
        float s[8][4];
        #pragma unroll
        for (int nf = 0; nf < 8; nf++)
            #pragma unroll
            for (int r = 0; r < 4; r++) s[nf][r] = 0.f;

        #pragma unroll
        for (int ks = 0; ks < 4; ks++) {
            int kb = ks * 16;
            #pragma unroll
            for (int p = 0; p < 4; p++) {
                uint32_t bk[4];
                ldsm4(bk, kaddr + (uint32_t)(p * 16 * SKH + kb) * 2u);
                mma_f16(s[2*p],   qf[ks][0], qf[ks][1], qf[ks][2], qf[ks][3], bk[0], bk[1]);
                mma_f16(s[2*p+1], qf[ks][0], qf[ks][1], qf[ks][2], qf[ks][3], bk[2], bk[3]);
            }
        }

        // ALiBi + causal + row max
        float rmax0 = -1e30f, rmax1 = -1e30f;
        if (k0 + 63 <= wmin) {
            #pragma unroll
            for (int nf = 0; nf < 8; nf++) {
                int kj = k0 + nf * 8 + 2 * lt;
                s[nf][0] += slope * (float)(kj - r0);
                s[nf][1] += slope * (float)(kj + 1 - r0);
                s[nf][2] += slope * (float)(kj - (r0 + 8));
                s[nf][3] += slope * (float)(kj + 1 - (r0 + 8));
                rmax0 = fmaxf(rmax0, fmaxf(s[nf][0], s[nf][1]));
                rmax1 = fmaxf(rmax1, fmaxf(s[nf][2], s[nf][3]));
            }
        } else {
            #pragma unroll
            for (int nf = 0; nf < 8; nf++) {
                int kj = k0 + nf * 8 + 2 * lt;
                int d00 = kj - r0, d01 = kj + 1 - r0;
                int d10 = kj - (r0 + 8), d11 = kj + 1 - (r0 + 8);
                s[nf][0] = (d00 <= 0) ? s[nf][0] + slope * (float)d00 : -1e30f;
                s[nf][1] = (d01 <= 0) ? s[nf][1] + slope * (float)d01 : -1e30f;
                s[nf][2] = (d10 <= 0) ? s[nf][2] + slope * (float)d10 : -1e30f;
                s[nf][3] = (d11 <= 0) ? s[nf][3] + slope * (float)d11 : -1e30f;
                rmax0 = fmaxf(rmax0, fmaxf(s[nf][0], s[nf][1]));
                rmax1 = fmaxf(rmax1, fmaxf(s[nf][2], s[nf][3]));
            }
        }
        rmax0 = fmaxf(rmax0, __shfl_xor_sync(0xffffffffu, rmax0, 1));
        rmax0 = fmaxf(rmax0, __shfl_xor_sync(0xffffffffu, rmax0, 2));
        rmax1 = fmaxf(rmax1, __shfl_xor_sync(0xffffffffu, rmax1, 1));
        rmax1 = fmaxf(rmax1, __shfl_xor_sync(0xffffffffu, rmax1, 2));

        float mn0 = fmaxf(m0, rmax0), mn1 = fmaxf(m1, rmax1);
        float c0 = ex2f(m0 - mn0),  c1 = ex2f(m1 - mn1);
        m0 = mn0; m1 = mn1;

        // P = exp2(S - m) -> swizzled SMEM, per-thread partial sums
        float rs0 = 0.f, rs1 = 0.f;
        #pragma unroll
        for (int nf = 0; nf < 8; nf++) {
            float p0 = ex2f(s[nf][0] - mn0);
            float p1 = ex2f(s[nf][1] - mn0);
            float p2 = ex2f(s[nf][2] - mn1);
            float p3 = ex2f(s[nf][3] - mn1);
            rs0 += p0 + p1;
            rs1 += p2 + p3;
            int swz = nf ^ lg;
            int c = (swz << 3) + 2 * lt;
            *(uint32_t*)&Pw[(lg << 6) + c]        = pack_h2(p0, p1);
            *(uint32_t*)&Pw[((lg + 8) << 6) + c]  = pack_h2(p2, p3);
        }
        lp0 = lp0 * c0 + rs0;
        lp1 = lp1 * c1 + rs1;

        #pragma unroll
        for (int nf = 0; nf < 8; nf++) {
            oacc[nf][0] *= c0; oacc[nf][1] *= c0;
            oacc[nf][2] *= c1; oacc[nf][3] *= c1;
        }

        __syncwarp();

        // O += P V
        #pragma unroll
        for (int ks = 0; ks < 4; ks++) {
            int kb = ks * 16;
            int pchunk = (2 * ks + (ah8 >> 3)) ^ (arow & 7);
            uint32_t a[4];
            ldsm4(a, pw_u32 + (uint32_t)((arow << 6) + (pchunk << 3)) * 2u);
            #pragma unroll
            for (int p = 0; p < 4; p++) {
                uint32_t bv[4];
                ldsm4t(bv, vaddr + (uint32_t)(kb * SKH + p * 16) * 2u);
                mma_f16(oacc[2*p],   a[0], a[1], a[2], a[3], bv[0], bv[1]);
                mma_f16(oacc[2*p+1], a[0], a[1], a[2], a[3], bv[2], bv[3]);
            }
        }
    }

    // Final l reduction + normalize + fp16 store.
    lp0 += __shfl_xor_sync(0xffffffffu, lp0, 1);
    lp0 += __shfl_xor_sync(0xffffffffu, lp0, 2);
    lp1 += __shfl_xor_sync(0xffffffffu, lp1, 1);
    lp1 += __shfl_xor_sync(0xffffffffu, lp1, 2);
    float inv0 = 1.f / lp0, inv1 = 1.f / lp1;
    __half* o0 = &g_oh[(size_t)(b * T_ + r0) * C_ + h * D_];
    __half* o1 = o0 + 8 * C_;
    #pragma unroll
    for (int nf = 0; nf < 8; nf++) {
        int c = nf * 8 + 2 * lt;
        *(uint32_t*)&o0[c] = pack_h2(oacc[nf][0] * inv0, oacc[nf][1] * inv0);
        *(uint32_t*)&o1[c] = pack_h2(oacc[nf][2] * inv1, oacc[nf][3] * inv1);
    }
}

// ---------------------------------------------------------------------------
extern "C" void kernel_launch(void* const* d_in, const int* in_sizes, int n_in,
                              void* d_out, int out_size)
{
    const float* x  = (const float*)d_in[0];
    const float* Wq = (const float*)d_in[1];
    const float* bq = (const float*)d_in[2];
    const float* Wk = (const float*)d_in[3];
    const float* bk = (const float*)d_in[4];
    const float* Wv = (const float*)d_in[5];
    const float* bv = (const float*)d_in[6];
    const float* Wo = (const float*)d_in[7];
    const float* bo = (const float*)d_in[8];
    float* out = (float*)d_out;

    cudaFuncSetAttribute(qkv_gemm_kernel,
                         cudaFuncAttributeMaxDynamicSharedMemorySize, GEMM_SMEM);
    cudaFuncSetAttribute(out_gemm_kernel,
                         cudaFuncAttributeMaxDynamicSharedMemorySize, GEMM_SMEM);
    cudaFuncSetAttribute(attn_mma_kernel,
                         cudaFuncAttributeMaxDynamicSharedMemorySize, ATT_SMEM);

    conv_all_kernel<<<2048, 256>>>(x, Wq, Wk, Wv, Wo);

    qkv_gemm_kernel<<<dim3(24, 32), 256, GEMM_SMEM>>>(bq, bk, bv);

    attn_mma_kernel<<<dim3(T_ / 128, H_, B_), 256, ATT_SMEM>>>();

    out_gemm_kernel<<<dim3(8, 32), 256, GEMM_SMEM>>>(bo, out);
}

// round 16
// speedup vs baseline: 1.0579x; 1.0579x over previous
#include <cuda_runtime.h>
#include <cuda_fp16.h>
#include <stdint.h>
#include <math.h>

#define B_ 2
#define T_ 2048
#define C_ 1024
#define H_ 16
#define D_ 64
#define M_ (B_*T_)   // 4096 rows

// Scratch (allocation-free).
__device__ __half g_qh[M_*C_];     // Q, pre-scaled by 0.125*log2e
__device__ __half g_kh[M_*C_];
__device__ __half g_vh[M_*C_];
__device__ __half g_oh[M_*C_];     // attention out
__device__ __half g_xh[M_*C_];     // x rounded to fp16
__device__ __half g_wh[4*C_*C_];   // W^T rounded to fp16: [sel][n][k]

__device__ __forceinline__ float ex2f(float x) {
    float y;
    asm("ex2.approx.ftz.f32 %0, %1;" : "=f"(y) : "f"(x));
    return y;
}

__device__ __forceinline__ void mma_f16(float c[4],
    uint32_t a0, uint32_t a1, uint32_t a2, uint32_t a3,
    uint32_t b0, uint32_t b1)
{
    asm volatile(
        "mma.sync.aligned.m16n8k16.row.col.f32.f16.f16.f32 "
        "{%0,%1,%2,%3},{%4,%5,%6,%7},{%8,%9},{%0,%1,%2,%3};"
        : "+f"(c[0]), "+f"(c[1]), "+f"(c[2]), "+f"(c[3])
        : "r"(a0), "r"(a1), "r"(a2), "r"(a3), "r"(b0), "r"(b1));
}

__device__ __forceinline__ void ldsm4(uint32_t r[4], uint32_t saddr) {
    asm volatile("ldmatrix.sync.aligned.m8n8.x4.shared.b16 {%0,%1,%2,%3}, [%4];"
        : "=r"(r[0]), "=r"(r[1]), "=r"(r[2]), "=r"(r[3]) : "r"(saddr));
}

__device__ __forceinline__ void ldsm4t(uint32_t r[4], uint32_t saddr) {
    asm volatile("ldmatrix.sync.aligned.m8n8.x4.trans.shared.b16 {%0,%1,%2,%3}, [%4];"
        : "=r"(r[0]), "=r"(r[1]), "=r"(r[2]), "=r"(r[3]) : "r"(saddr));
}

__device__ __forceinline__ void cpa16(void* dst, const void* src) {
    uint32_t d = (uint32_t)__cvta_generic_to_shared(dst);
    asm volatile("cp.async.cg.shared.global [%0], [%1], 16;" :: "r"(d), "l"(src));
}
#define CP_COMMIT() asm volatile("cp.async.commit_group;")
#define CP_WAIT(N)  asm volatile("cp.async.wait_group %0;" :: "n"(N))

__device__ __forceinline__ uint32_t pack_h2(float a, float b) {
    __half2 h = __floats2half2_rn(a, b);
    return *(uint32_t*)&h;
}

// ---------------------------------------------------------------------------
// Fused conversion: blocks [0,1024) x fp32->fp16; [1024,2048) W round+transpose.
// ---------------------------------------------------------------------------
__global__ __launch_bounds__(256) void conv_all_kernel(
    const float* __restrict__ x,
    const float* __restrict__ Wq, const float* __restrict__ Wk,
    const float* __restrict__ Wv, const float* __restrict__ Wo)
{
    __shared__ __half tile[64][68];
    if (blockIdx.x < 1024) {
        #pragma unroll
        for (int l = 0; l < 4; l++) {
            int i4 = blockIdx.x * 1024 + l * 256 + threadIdx.x;
            float4 v = *(const float4*)&x[(size_t)i4 << 2];
            uint2 u = { pack_h2(v.x, v.y), pack_h2(v.z, v.w) };
            *(uint2*)&g_xh[(size_t)i4 << 2] = u;
        }
        return;
    }
    const float* Ws[4] = { Wq, Wk, Wv, Wo };
    int bx  = blockIdx.x - 1024;
    int mat = bx >> 8;
    int t   = bx & 255;
    int kb  = (t >> 4) << 6;
    int nb  = (t & 15) << 6;
    const float* W = Ws[mat];
    int tid = threadIdx.x;
    int rr = tid >> 4, c4 = (tid & 15) << 2;
    #pragma unroll
    for (int l = 0; l < 4; l++) {
        int row = rr + l * 16;
        float4 v = *(const float4*)&W[(size_t)(kb + row) * C_ + nb + c4];
        tile[row][c4 + 0] = __float2half_rn(v.x);
        tile[row][c4 + 1] = __float2half_rn(v.y);
        tile[row][c4 + 2] = __float2half_rn(v.z);
        tile[row][c4 + 3] = __float2half_rn(v.w);
    }
    __syncthreads();
    __half* dst = g_wh + ((size_t)mat << 20);
    #pragma unroll
    for (int l = 0; l < 4; l++) {
        int row = rr + l * 16;
        __half2 p0 = __halves2half2(tile[c4 + 0][row], tile[c4 + 1][row]);
        __half2 p1 = __halves2half2(tile[c4 + 2][row], tile[c4 + 3][row]);
        uint2 u = { *(uint32_t*)&p0, *(uint32_t*)&p1 };
        *(uint2*)&dst[(size_t)(nb + row) * C_ + kb + c4] = u;
    }
}

// ---------------------------------------------------------------------------
// FP16 GEMM (m16n8k16): R13 configuration + k-loop unrolled by 3 (stage
// rotation period) so stage bases are compile-time constants per copy.
// ---------------------------------------------------------------------------
#define SAH 72
#define STG_H (256*SAH)             // 18432 halves per stage
#define GEMM_SMEM (3*STG_H*2)       // 110592 bytes

__device__ __forceinline__ void gemm_issue(
    __half* stage, const __half* A, const __half* Wt,
    int brow, int bcol, int k0, int tid)
{
    __half* As = stage;
    __half* Ws = stage + 128 * SAH;
    #pragma unroll
    for (int l = 0; l < 8; l++) {
        int idx = tid + (l << 8);
        int row = idx >> 3;
        int c16 = (idx & 7) << 3;
        if (row < 128)
            cpa16(&As[row * SAH + c16], &A[(size_t)(brow + row) * C_ + k0 + c16]);
        else
            cpa16(&Ws[(row - 128) * SAH + c16],
                  &Wt[(size_t)(bcol + row - 128) * C_ + k0 + c16]);
    }
}

__device__ __forceinline__ void gemm_pipe(
    const __half* __restrict__ A, const __half* __restrict__ Wt,
    const float* __restrict__ bias, void* __restrict__ Cm,
    int brow, int bcol, int outHalf, float sc)
{
    extern __shared__ __half smh[];
    const int tid  = threadIdx.x;
    const int lane = tid & 31;
    const int warp = tid >> 5;
    const int wr   = warp >> 2;
    const int wc   = warp & 3;
    const int lg   = lane >> 2;
    const int lt   = lane & 3;

    const int arow = lane & 15;
    const int ah8  = ((lane >> 4) & 1) * 8;
    const int brw  = ((lane >> 4) & 1) * 8 + (lane & 7);
    const int bh8  = ((lane >> 3) & 1) * 8;
    const uint32_t smem_u32 = (uint32_t)__cvta_generic_to_shared(smh);

    float acc[4][4][4];
    #pragma unroll
    for (int mf = 0; mf < 4; mf++)
        #pragma unroll
        for (int nf = 0; nf < 4; nf++)
            #pragma unroll
            for (int r = 0; r < 4; r++) acc[mf][nf][r] = 0.f;

    gemm_issue(smh,         A, Wt, brow, bcol, 0,  tid); CP_COMMIT();
    gemm_issue(smh + STG_H, A, Wt, brow, bcol, 64, tid); CP_COMMIT();

    const int NIT = C_ / 64;   // 16
    #pragma unroll 3
    for (int it = 0; it < NIT; it++) {
        CP_WAIT(1);
        __syncthreads();
        int kn = (it + 2) * 64;
        if (kn < C_) gemm_issue(smh + ((it + 2) % 3) * STG_H, A, Wt, brow, bcol, kn, tid);
        CP_COMMIT();

        uint32_t sbase = smem_u32 + (uint32_t)((it % 3) * STG_H) * 2u;
        uint32_t aaddr = sbase + (uint32_t)((wr * 64 + arow) * SAH + ah8) * 2u;
        uint32_t baddr = sbase + (uint32_t)(128 * SAH) * 2u
                       + (uint32_t)((wc * 32 + brw) * SAH + bh8) * 2u;

        #pragma unroll
        for (int ks = 0; ks < 4; ks++) {
            const int kb = ks * 16;
            uint32_t b0[4], b1[4];
            ldsm4(b0, baddr + (uint32_t)kb * 2u);
            ldsm4(b1, baddr + (uint32_t)(16 * SAH + kb) * 2u);
            #pragma unroll
            for (int mf = 0; mf < 4; mf++) {
                uint32_t a[4];
                ldsm4(a, aaddr + (uint32_t)(mf * 16 * SAH + kb) * 2u);
                mma_f16(acc[mf][0], a[0], a[1], a[2], a[3], b0[0], b0[1]);
                mma_f16(acc[mf][1], a[0], a[1], a[2], a[3], b0[2], b0[3]);
                mma_f16(acc[mf][2], a[0], a[1], a[2], a[3], b1[0], b1[1]);
                mma_f16(acc[mf][3], a[0], a[1], a[2], a[3], b1[2], b1[3]);
            }
        }
    }

    #pragma unroll
    for (int mf = 0; mf < 4; mf++) {
        int row0 = brow + wr * 64 + mf * 16 + lg;
        #pragma unroll
        for (int nf = 0; nf < 4; nf++) {
            int col = bcol + wc * 32 + nf * 8 + lt * 2;
            float bx = bias[col], by = bias[col + 1];
            float v00 = (acc[mf][nf][0] + bx) * sc, v01 = (acc[mf][nf][1] + by) * sc;
            float v10 = (acc[mf][nf][2] + bx) * sc, v11 = (acc[mf][nf][3] + by) * sc;
            if (outHalf) {
                __half* Ch = (__half*)Cm;
                uint32_t o0 = pack_h2(v00, v01), o1 = pack_h2(v10, v11);
                *(uint32_t*)&Ch[(size_t)row0 * C_ + col]       = o0;
                *(uint32_t*)&Ch[(size_t)(row0 + 8) * C_ + col] = o1;
            } else {
                float* Cf = (float*)Cm;
                float2 o0 = { v00, v01 };
                float2 o1 = { v10, v11 };
                *(float2*)&Cf[(size_t)row0 * C_ + col]       = o0;
                *(float2*)&Cf[(size_t)(row0 + 8) * C_ + col] = o1;
            }
        }
    }
}

__global__ __launch_bounds__(256) void qkv_gemm_kernel(
    const float* __restrict__ bq, const float* __restrict__ bk,
    const float* __restrict__ bv)
{
    int sel  = blockIdx.x >> 3;
    int bcol = (blockIdx.x & 7) * 128;
    int brow = blockIdx.y * 128;
    const __half* Wt  = g_wh + ((size_t)sel << 20);
    const float* bias = (sel == 0) ? bq : (sel == 1) ? bk : bv;
    __half* Cm        = (sel == 0) ? g_qh : (sel == 1) ? g_kh : g_vh;
    float sc = (sel == 0) ? 0.125f * 1.4426950408889634f : 1.0f;
    gemm_pipe(g_xh, Wt, bias, Cm, brow, bcol, 1, sc);
}

__global__ __launch_bounds__(256) void out_gemm_kernel(
    const float* __restrict__ bo, float* __restrict__ out)
{
    gemm_pipe(g_oh, g_wh + ((size_t)3 << 20), bo, out,
              blockIdx.y * 128, blockIdx.x * 128, 0, 1.0f);
}

// ---------------------------------------------------------------------------
// FP16 flash attention (m16n8k16), ALiBi + causal. R13 configuration
// (64-query CTA, 4 warps, 4 CTA/SM) + tile loop unrolled by 2 (buffer period).
// ---------------------------------------------------------------------------
#define SKH 72
#define AST_H (128*SKH)                   // 9216 halves per KV stage
#define PS_OFFH (2*AST_H)                 // P region offset in halves
#define ATT_SMEM ((2*AST_H + 64*64)*2)    // 45056 bytes

__device__ __forceinline__ void attn_issue_kv(
    __half* stage, int b, int h, int k0, int tid)
{
    __half* Ks = stage;
    __half* Vs = stage + 64 * SKH;
    #pragma unroll
    for (int l = 0; l < 8; l++) {
        int idx = tid + (l << 7);
        int row = idx >> 3;
        int c16 = (idx & 7) << 3;
        if (row < 64)
            cpa16(&Ks[row * SKH + c16],
                  &g_kh[(size_t)(b * T_ + k0 + row) * C_ + h * D_ + c16]);
        else
            cpa16(&Vs[(row - 64) * SKH + c16],
                  &g_vh[(size_t)(b * T_ + k0 + row - 64) * C_ + h * D_ + c16]);
    }
}

__global__ __launch_bounds__(128) void attn_mma_kernel()
{
    extern __shared__ __half smh[];

    const int tid  = threadIdx.x;
    const int lane = tid & 31;
    const int warp = tid >> 5;
    const int lg   = lane >> 2;
    const int lt   = lane & 3;
    const int h    = blockIdx.y;
    const int b    = blockIdx.z;
    const int qbase = (gridDim.x - 1 - blockIdx.x) * 64;   // heavy-first

    const float slope = exp2f(-0.5f * (float)(h + 1)) * 1.4426950408889634f;

    const int arow = lane & 15;
    const int ah8  = ((lane >> 4) & 1) * 8;
    const int brw  = ((lane >> 4) & 1) * 8 + (lane & 7);
    const int bh8  = ((lane >> 3) & 1) * 8;
    const uint32_t sm_u32 = (uint32_t)__cvta_generic_to_shared(smh);

    const int wmin = qbase + warp * 16;
    const int r0 = wmin + lg;

    uint32_t qf[4][4];
    {
        const __half* q0 = &g_qh[(size_t)(b * T_ + r0) * C_ + h * D_];
        const __half* q1 = q0 + 8 * C_;
        #pragma unroll
        for (int ks = 0; ks < 4; ks++) {
            int c = ks * 16 + 2 * lt;
            qf[ks][0] = *(const uint32_t*)&q0[c];
            qf[ks][1] = *(const uint32_t*)&q1[c];
            qf[ks][2] = *(const uint32_t*)&q0[c + 8];
            qf[ks][3] = *(const uint32_t*)&q1[c + 8];
        }
    }

    float oacc[8][4];
    #pragma unroll
    for (int nf = 0; nf < 8; nf++)
        #pragma unroll
        for (int r = 0; r < 4; r++) oacc[nf][r] = 0.f;
    float m0 = -1e30f, m1 = -1e30f;
    float lp0 = 0.f, lp1 = 0.f;     // per-thread partial row sums (deferred)

    const int ntiles = qbase / 64 + 1;
    __half* Pw = smh + PS_OFFH + warp * 16 * 64;
    const uint32_t pw_u32 = sm_u32 + (uint32_t)(PS_OFFH + warp * 16 * 64) * 2u;

    attn_issue_kv(smh, b, h, 0, tid); CP_COMMIT();

    #pragma unroll 2
    for (int t = 0; t < ntiles; t++) {
        CP_WAIT(0);
        __syncthreads();
        if (t + 1 < ntiles)
            attn_issue_kv(smh + ((t + 1) & 1) * AST_H, b, h, (t + 1) * 64, tid);
        CP_COMMIT();

        const int k0 = t * 64;
        const uint32_t st_u32 = sm_u32 + (uint32_t)((t & 1) * AST_H) * 2u;
        const uint32_t kaddr  = st_u32 + (uint32_t)(brw * SKH + bh8) * 2u;
        const uint32_t vaddr  = st_u32 + (uint32_t)(64 * SKH) * 2u
                              + (uint32_t)(arow * SKH + ah8) * 2u;

        float s[8][4];
        #pragma unroll
        for (int nf = 0; nf < 8; nf++)
            #pragma unroll
            for (int r = 0; r < 4; r++) s[nf][r] = 0.f;

        #pragma unroll
        for (int ks = 0; ks < 4; ks++) {
            int kb = ks * 16;
            #pragma unroll
            for (int p = 0; p < 4; p++) {
                uint32_t bk[4];
                ldsm4(bk, kaddr + (uint32_t)(p * 16 * SKH + kb) * 2u);
                mma_f16(s[2*p],   qf[ks][0], qf[ks][1], qf[ks][2], qf[ks][3], bk[0], bk[1]);
                mma_f16(s[2*p+1], qf[ks][0], qf[ks][1], qf[ks][2], qf[ks][3], bk[2], bk[3]);
            }
        }

        float rmax0 = -1e30f, rmax1 = -1e30f;
        if (k0 + 63 <= wmin) {
            #pragma unroll
            for (int nf = 0; nf < 8; nf++) {
                int kj = k0 + nf * 8 + 2 * lt;
                s[nf][0] += slope * (float)(kj - r0);
                s[nf][1] += slope * (float)(kj + 1 - r0);
                s[nf][2] += slope * (float)(kj - (r0 + 8));
                s[nf][3] += slope * (float)(kj + 1 - (r0 + 8));
                rmax0 = fmaxf(rmax0, fmaxf(s[nf][0], s[nf][1]));
                rmax1 = fmaxf(rmax1, fmaxf(s[nf][2], s[nf][3]));
            }
        } else {
            #pragma unroll
            for (int nf = 0; nf < 8; nf++) {
                int kj = k0 + nf * 8 + 2 * lt;
                int d00 = kj - r0, d01 = kj + 1 - r0;
                int d10 = kj - (r0 + 8), d11 = kj + 1 - (r0 + 8);
                s[nf][0] = (d00 <= 0) ? s[nf][0] + slope * (float)d00 : -1e30f;
                s[nf][1] = (d01 <= 0) ? s[nf][1] + slope * (float)d01 : -1e30f;
                s[nf][2] = (d10 <= 0) ? s[nf][2] + slope * (float)d10 : -1e30f;
                s[nf][3] = (d11 <= 0) ? s[nf][3] + slope * (float)d11 : -1e30f;
                rmax0 = fmaxf(rmax0, fmaxf(s[nf][0], s[nf][1]));
                rmax1 = fmaxf(rmax1, fmaxf(s[nf][2], s[nf][3]));
            }
        }
        rmax0 = fmaxf(rmax0, __shfl_xor_sync(0xffffffffu, rmax0, 1));
        rmax0 = fmaxf(rmax0, __shfl_xor_sync(0xffffffffu, rmax0, 2));
        rmax1 = fmaxf(rmax1, __shfl_xor_sync(0xffffffffu, rmax1, 1));
        rmax1 = fmaxf(rmax1, __shfl_xor_sync(0xffffffffu, rmax1, 2));

        float mn0 = fmaxf(m0, rmax0), mn1 = fmaxf(m1, rmax1);
        float c0 = ex2f(m0 - mn0),  c1 = ex2f(m1 - mn1);
        m0 = mn0; m1 = mn1;

        float rs0 = 0.f, rs1 = 0.f;
        #pragma unroll
        for (int nf = 0; nf < 8; nf++) {
            float p0 = ex2f(s[nf][0] - mn0);
            float p1 = ex2f(s[nf][1] - mn0);
            float p2 = ex2f(s[nf][2] - mn1);
            float p3 = ex2f(s[nf][3] - mn1);
            rs0 += p0 + p1;
            rs1 += p2 + p3;
            int swz = nf ^ lg;
            int c = (swz << 3) + 2 * lt;
            *(uint32_t*)&Pw[(lg << 6) + c]        = pack_h2(p0, p1);
            *(uint32_t*)&Pw[((lg + 8) << 6) + c]  = pack_h2(p2, p3);
        }
        lp0 = lp0 * c0 + rs0;
        lp1 = lp1 * c1 + rs1;

        #pragma unroll
        for (int nf = 0; nf < 8; nf++) {
            oacc[nf][0] *= c0; oacc[nf][1] *= c0;
            oacc[nf][2] *= c1; oacc[nf][3] *= c1;
        }

        __syncwarp();

        #pragma unroll
        for (int ks = 0; ks < 4; ks++) {
            int kb = ks * 16;
            int pchunk = (2 * ks + (ah8 >> 3)) ^ (arow & 7);
            uint32_t a[4];
            ldsm4(a, pw_u32 + (uint32_t)((arow << 6) + (pchunk << 3)) * 2u);
            #pragma unroll
            for (int p = 0; p < 4; p++) {
                uint32_t bv[4];
                ldsm4t(bv, vaddr + (uint32_t)(kb * SKH + p * 16) * 2u);
                mma_f16(oacc[2*p],   a[0], a[1], a[2], a[3], bv[0], bv[1]);
                mma_f16(oacc[2*p+1], a[0], a[1], a[2], a[3], bv[2], bv[3]);
            }
        }
    }

    lp0 += __shfl_xor_sync(0xffffffffu, lp0, 1);
    lp0 += __shfl_xor_sync(0xffffffffu, lp0, 2);
    lp1 += __shfl_xor_sync(0xffffffffu, lp1, 1);
    lp1 += __shfl_xor_sync(0xffffffffu, lp1, 2);
    float inv0 = 1.f / lp0, inv1 = 1.f / lp1;
    __half* o0 = &g_oh[(size_t)(b * T_ + r0) * C_ + h * D_];
    __half* o1 = o0 + 8 * C_;
    #pragma unroll
    for (int nf = 0; nf < 8; nf++) {
        int c = nf * 8 + 2 * lt;
        *(uint32_t*)&o0[c] = pack_h2(oacc[nf][0] * inv0, oacc[nf][1] * inv0);
        *(uint32_t*)&o1[c] = pack_h2(oacc[nf][2] * inv1, oacc[nf][3] * inv1);
    }
}

// ---------------------------------------------------------------------------
extern "C" void kernel_launch(void* const* d_in, const int* in_sizes, int n_in,
                              void* d_out, int out_size)
{
    const float* x  = (const float*)d_in[0];
    const float* Wq = (const float*)d_in[1];
    const float* bq = (const float*)d_in[2];
    const float* Wk = (const float*)d_in[3];
    const float* bk = (const float*)d_in[4];
    const float* Wv = (const float*)d_in[5];
    const float* bv = (const float*)d_in[6];
    const float* Wo = (const float*)d_in[7];
    const float* bo = (const float*)d_in[8];
    float* out = (float*)d_out;

    cudaFuncSetAttribute(qkv_gemm_kernel,
                         cudaFuncAttributeMaxDynamicSharedMemorySize, GEMM_SMEM);
    cudaFuncSetAttribute(out_gemm_kernel,
                         cudaFuncAttributeMaxDynamicSharedMemorySize, GEMM_SMEM);
    cudaFuncSetAttribute(attn_mma_kernel,
                         cudaFuncAttributeMaxDynamicSharedMemorySize, ATT_SMEM);

    conv_all_kernel<<<2048, 256>>>(x, Wq, Wk, Wv, Wo);

    qkv_gemm_kernel<<<dim3(24, 32), 256, GEMM_SMEM>>>(bq, bk, bv);

    attn_mma_kernel<<<dim3(T_ / 64, H_, B_), 128, ATT_SMEM>>>();

    out_gemm_kernel<<<dim3(8, 32), 256, GEMM_SMEM>>>(bo, out);
}

// round 17
// speedup vs baseline: 1.0684x; 1.0099x over previous
#include <cuda_runtime.h>
#include <cuda_fp16.h>
#include <stdint.h>
#include <math.h>

#define B_ 2
#define T_ 2048
#define C_ 1024
#define H_ 16
#define D_ 64
#define M_ (B_*T_)   // 4096 rows

// Scratch (allocation-free).
__device__ __half g_qh[M_*C_];     // Q, pre-scaled by 0.125*log2e
__device__ __half g_kh[M_*C_];
__device__ __half g_vh[M_*C_];
__device__ __half g_oh[M_*C_];     // attention out
__device__ __half g_xh[M_*C_];     // x rounded to fp16
__device__ __half g_wh[4*C_*C_];   // W^T rounded to fp16: [sel][n][k]

__device__ __forceinline__ float ex2f(float x) {
    float y;
    asm("ex2.approx.ftz.f32 %0, %1;" : "=f"(y) : "f"(x));
    return y;
}

__device__ __forceinline__ void mma_f16(float c[4],
    uint32_t a0, uint32_t a1, uint32_t a2, uint32_t a3,
    uint32_t b0, uint32_t b1)
{
    asm volatile(
        "mma.sync.aligned.m16n8k16.row.col.f32.f16.f16.f32 "
        "{%0,%1,%2,%3},{%4,%5,%6,%7},{%8,%9},{%0,%1,%2,%3};"
        : "+f"(c[0]), "+f"(c[1]), "+f"(c[2]), "+f"(c[3])
        : "r"(a0), "r"(a1), "r"(a2), "r"(a3), "r"(b0), "r"(b1));
}

__device__ __forceinline__ void ldsm4(uint32_t r[4], uint32_t saddr) {
    asm volatile("ldmatrix.sync.aligned.m8n8.x4.shared.b16 {%0,%1,%2,%3}, [%4];"
        : "=r"(r[0]), "=r"(r[1]), "=r"(r[2]), "=r"(r[3]) : "r"(saddr));
}

__device__ __forceinline__ void ldsm4t(uint32_t r[4], uint32_t saddr) {
    asm volatile("ldmatrix.sync.aligned.m8n8.x4.trans.shared.b16 {%0,%1,%2,%3}, [%4];"
        : "=r"(r[0]), "=r"(r[1]), "=r"(r[2]), "=r"(r[3]) : "r"(saddr));
}

__device__ __forceinline__ void cpa16(void* dst, const void* src) {
    uint32_t d = (uint32_t)__cvta_generic_to_shared(dst);
    asm volatile("cp.async.cg.shared.global [%0], [%1], 16;" :: "r"(d), "l"(src));
}
#define CP_COMMIT() asm volatile("cp.async.commit_group;")
#define CP_WAIT(N)  asm volatile("cp.async.wait_group %0;" :: "n"(N))

__device__ __forceinline__ uint32_t pack_h2(float a, float b) {
    __half2 h = __floats2half2_rn(a, b);
    return *(uint32_t*)&h;
}

// ---------------------------------------------------------------------------
// Fused conversion: blocks [0,1024) x fp32->fp16; [1024,2048) W round+transpose.
// ---------------------------------------------------------------------------
__global__ __launch_bounds__(256) void conv_all_kernel(
    const float* __restrict__ x,
    const float* __restrict__ Wq, const float* __restrict__ Wk,
    const float* __restrict__ Wv, const float* __restrict__ Wo)
{
    __shared__ __half tile[64][68];
    if (blockIdx.x < 1024) {
        #pragma unroll
        for (int l = 0; l < 4; l++) {
            int i4 = blockIdx.x * 1024 + l * 256 + threadIdx.x;
            float4 v = *(const float4*)&x[(size_t)i4 << 2];
            uint2 u = { pack_h2(v.x, v.y), pack_h2(v.z, v.w) };
            *(uint2*)&g_xh[(size_t)i4 << 2] = u;
        }
        return;
    }
    const float* Ws[4] = { Wq, Wk, Wv, Wo };
    int bx  = blockIdx.x - 1024;
    int mat = bx >> 8;
    int t   = bx & 255;
    int kb  = (t >> 4) << 6;
    int nb  = (t & 15) << 6;
    const float* W = Ws[mat];
    int tid = threadIdx.x;
    int rr = tid >> 4, c4 = (tid & 15) << 2;
    #pragma unroll
    for (int l = 0; l < 4; l++) {
        int row = rr + l * 16;
        float4 v = *(const float4*)&W[(size_t)(kb + row) * C_ + nb + c4];
        tile[row][c4 + 0] = __float2half_rn(v.x);
        tile[row][c4 + 1] = __float2half_rn(v.y);
        tile[row][c4 + 2] = __float2half_rn(v.z);
        tile[row][c4 + 3] = __float2half_rn(v.w);
    }
    __syncthreads();
    __half* dst = g_wh + ((size_t)mat << 20);
    #pragma unroll
    for (int l = 0; l < 4; l++) {
        int row = rr + l * 16;
        __half2 p0 = __halves2half2(tile[c4 + 0][row], tile[c4 + 1][row]);
        __half2 p1 = __halves2half2(tile[c4 + 2][row], tile[c4 + 3][row]);
        uint2 u = { *(uint32_t*)&p0, *(uint32_t*)&p1 };
        *(uint2*)&dst[(size_t)(nb + row) * C_ + kb + c4] = u;
    }
}

// ---------------------------------------------------------------------------
// FP16 GEMM (m16n8k16): CTA 64x128 tile, 128 thr (4 warps side-by-side,
// warp 64x32 = R13 warp shape). BK=64, 2-stage cp.async, 4 CTA/SM.
// ---------------------------------------------------------------------------
#define SAH 72
#define STG_H (192*SAH)             // 13824 halves per stage (64 A + 128 B rows)
#define GEMM_SMEM (2*STG_H*2)       // 55296 bytes

__device__ __forceinline__ void gemm_issue(
    __half* stage, const __half* A, const __half* Wt,
    int brow, int bcol, int k0, int tid)
{
    __half* As = stage;                  // 64 rows
    __half* Ws = stage + 64 * SAH;       // 128 rows
    #pragma unroll
    for (int l = 0; l < 12; l++) {
        int idx = tid + (l << 7);
        int row = idx >> 3;              // 0..191
        int c16 = (idx & 7) << 3;
        if (row < 64)
            cpa16(&As[row * SAH + c16], &A[(size_t)(brow + row) * C_ + k0 + c16]);
        else
            cpa16(&Ws[(row - 64) * SAH + c16],
                  &Wt[(size_t)(bcol + row - 64) * C_ + k0 + c16]);
    }
}

__device__ __forceinline__ void gemm_pipe(
    const __half* __restrict__ A, const __half* __restrict__ Wt,
    const float* __restrict__ bias, void* __restrict__ Cm,
    int brow, int bcol, int outHalf, float sc)
{
    extern __shared__ __half smh[];
    const int tid  = threadIdx.x;
    const int lane = tid & 31;
    const int warp = tid >> 5;           // 0..3 -> 32-col band
    const int lg   = lane >> 2;
    const int lt   = lane & 3;

    const int arow = lane & 15;
    const int ah8  = ((lane >> 4) & 1) * 8;
    const int brw  = ((lane >> 4) & 1) * 8 + (lane & 7);
    const int bh8  = ((lane >> 3) & 1) * 8;
    const uint32_t smem_u32 = (uint32_t)__cvta_generic_to_shared(smh);

    float acc[4][4][4];
    #pragma unroll
    for (int mf = 0; mf < 4; mf++)
        #pragma unroll
        for (int nf = 0; nf < 4; nf++)
            #pragma unroll
            for (int r = 0; r < 4; r++) acc[mf][nf][r] = 0.f;

    gemm_issue(smh, A, Wt, brow, bcol, 0, tid); CP_COMMIT();

    const int NIT = C_ / 64;   // 16
    #pragma unroll 2
    for (int it = 0; it < NIT; it++) {
        CP_WAIT(0);
        __syncthreads();
        if (it + 1 < NIT)
            gemm_issue(smh + ((it + 1) & 1) * STG_H, A, Wt, brow, bcol, (it + 1) * 64, tid);
        CP_COMMIT();

        uint32_t sbase = smem_u32 + (uint32_t)((it & 1) * STG_H) * 2u;
        uint32_t aaddr = sbase + (uint32_t)(arow * SAH + ah8) * 2u;
        uint32_t baddr = sbase + (uint32_t)(64 * SAH) * 2u
                       + (uint32_t)((warp * 32 + brw) * SAH + bh8) * 2u;

        #pragma unroll
        for (int ks = 0; ks < 4; ks++) {
            const int kb = ks * 16;
            uint32_t b0[4], b1[4];
            ldsm4(b0, baddr + (uint32_t)kb * 2u);
            ldsm4(b1, baddr + (uint32_t)(16 * SAH + kb) * 2u);
            #pragma unroll
            for (int mf = 0; mf < 4; mf++) {
                uint32_t a[4];
                ldsm4(a, aaddr + (uint32_t)(mf * 16 * SAH + kb) * 2u);
                mma_f16(acc[mf][0], a[0], a[1], a[2], a[3], b0[0], b0[1]);
                mma_f16(acc[mf][1], a[0], a[1], a[2], a[3], b0[2], b0[3]);
                mma_f16(acc[mf][2], a[0], a[1], a[2], a[3], b1[0], b1[1]);
                mma_f16(acc[mf][3], a[0], a[1], a[2], a[3], b1[2], b1[3]);
            }
        }
    }

    #pragma unroll
    for (int mf = 0; mf < 4; mf++) {
        int row0 = brow + mf * 16 + lg;
        #pragma unroll
        for (int nf = 0; nf < 4; nf++) {
            int col = bcol + warp * 32 + nf * 8 + lt * 2;
            float bx = bias[col], by = bias[col + 1];
            float v00 = (acc[mf][nf][0] + bx) * sc, v01 = (acc[mf][nf][1] + by) * sc;
            float v10 = (acc[mf][nf][2] + bx) * sc, v11 = (acc[mf][nf][3] + by) * sc;
            if (outHalf) {
                __half* Ch = (__half*)Cm;
                uint32_t o0 = pack_h2(v00, v01), o1 = pack_h2(v10, v11);
                *(uint32_t*)&Ch[(size_t)row0 * C_ + col]       = o0;
                *(uint32_t*)&Ch[(size_t)(row0 + 8) * C_ + col] = o1;
            } else {
                float* Cf = (float*)Cm;
                float2 o0 = { v00, v01 };
                float2 o1 = { v10, v11 };
                *(float2*)&Cf[(size_t)row0 * C_ + col]       = o0;
                *(float2*)&Cf[(size_t)(row0 + 8) * C_ + col] = o1;
            }
        }
    }
}

__global__ __launch_bounds__(128) void qkv_gemm_kernel(
    const float* __restrict__ bq, const float* __restrict__ bk,
    const float* __restrict__ bv)
{
    int sel  = blockIdx.x >> 3;
    int bcol = (blockIdx.x & 7) * 128;
    int brow = blockIdx.y * 64;
    const __half* Wt  = g_wh + ((size_t)sel << 20);
    const float* bias = (sel == 0) ? bq : (sel == 1) ? bk : bv;
    __half* Cm        = (sel == 0) ? g_qh : (sel == 1) ? g_kh : g_vh;
    float sc = (sel == 0) ? 0.125f * 1.4426950408889634f : 1.0f;
    gemm_pipe(g_xh, Wt, bias, Cm, brow, bcol, 1, sc);
}

__global__ __launch_bounds__(128) void out_gemm_kernel(
    const float* __restrict__ bo, float* __restrict__ out)
{
    gemm_pipe(g_oh, g_wh + ((size_t)3 << 20), bo, out,
              blockIdx.y * 64, blockIdx.x * 128, 0, 1.0f);
}

// ---------------------------------------------------------------------------
// FP16 flash attention (m16n8k16), ALiBi + causal. R16 version (proven best).
// ---------------------------------------------------------------------------
#define SKH 72
#define AST_H (128*SKH)                   // 9216 halves per KV stage
#define PS_OFFH (2*AST_H)                 // P region offset in halves
#define ATT_SMEM ((2*AST_H + 64*64)*2)    // 45056 bytes

__device__ __forceinline__ void attn_issue_kv(
    __half* stage, int b, int h, int k0, int tid)
{
    __half* Ks = stage;
    __half* Vs = stage + 64 * SKH;
    #pragma unroll
    for (int l = 0; l < 8; l++) {
        int idx = tid + (l << 7);
        int row = idx >> 3;
        int c16 = (idx & 7) << 3;
        if (row < 64)
            cpa16(&Ks[row * SKH + c16],
                  &g_kh[(size_t)(b * T_ + k0 + row) * C_ + h * D_ + c16]);
        else
            cpa16(&Vs[(row - 64) * SKH + c16],
                  &g_vh[(size_t)(b * T_ + k0 + row - 64) * C_ + h * D_ + c16]);
    }
}

__global__ __launch_bounds__(128) void attn_mma_kernel()
{
    extern __shared__ __half smh[];

    const int tid  = threadIdx.x;
    const int lane = tid & 31;
    const int warp = tid >> 5;
    const int lg   = lane >> 2;
    const int lt   = lane & 3;
    const int h    = blockIdx.y;
    const int b    = blockIdx.z;
    const int qbase = (gridDim.x - 1 - blockIdx.x) * 64;   // heavy-first

    const float slope = exp2f(-0.5f * (float)(h + 1)) * 1.4426950408889634f;

    const int arow = lane & 15;
    const int ah8  = ((lane >> 4) & 1) * 8;
    const int brw  = ((lane >> 4) & 1) * 8 + (lane & 7);
    const int bh8  = ((lane >> 3) & 1) * 8;
    const uint32_t sm_u32 = (uint32_t)__cvta_generic_to_shared(smh);

    const int wmin = qbase + warp * 16;
    const int r0 = wmin + lg;

    uint32_t qf[4][4];
    {
        const __half* q0 = &g_qh[(size_t)(b * T_ + r0) * C_ + h * D_];
        const __half* q1 = q0 + 8 * C_;
        #pragma unroll
        for (int ks = 0; ks < 4; ks++) {
            int c = ks * 16 + 2 * lt;
            qf[ks][0] = *(const uint32_t*)&q0[c];
            qf[ks][1] = *(const uint32_t*)&q1[c];
            qf[ks][2] = *(const uint32_t*)&q0[c + 8];
            qf[ks][3] = *(const uint32_t*)&q1[c + 8];
        }
    }

    float oacc[8][4];
    #pragma unroll
    for (int nf = 0; nf < 8; nf++)
        #pragma unroll
        for (int r = 0; r < 4; r++) oacc[nf][r] = 0.f;
    float m0 = -1e30f, m1 = -1e30f;
    float lp0 = 0.f, lp1 = 0.f;

    const int ntiles = qbase / 64 + 1;
    __half* Pw = smh + PS_OFFH + warp * 16 * 64;
    const uint32_t pw_u32 = sm_u32 + (uint32_t)(PS_OFFH + warp * 16 * 64) * 2u;

    attn_issue_kv(smh, b, h, 0, tid); CP_COMMIT();

    #pragma unroll 2
    for (int t = 0; t < ntiles; t++) {
        CP_WAIT(0);
        __syncthreads();
        if (t + 1 < ntiles)
            attn_issue_kv(smh + ((t + 1) & 1) * AST_H, b, h, (t + 1) * 64, tid);
        CP_COMMIT();

        const int k0 = t * 64;
        const uint32_t st_u32 = sm_u32 + (uint32_t)((t & 1) * AST_H) * 2u;
        const uint32_t kaddr  = st_u32 + (uint32_t)(brw * SKH + bh8) * 2u;
        const uint32_t vaddr  = st_u32 + (uint32_t)(64 * SKH) * 2u
                              + (uint32_t)(arow * SKH + ah8) * 2u;

        float s[8][4];
        #pragma unroll
        for (int nf = 0; nf < 8; nf++)
            #pragma unroll
            for (int r = 0; r < 4; r++) s[nf][r] = 0.f;

        #pragma unroll
        for (int ks = 0; ks < 4; ks++) {
            int kb = ks * 16;
            #pragma unroll
            for (int p = 0; p < 4; p++) {
                uint32_t bk[4];
                ldsm4(bk, kaddr + (uint32_t)(p * 16 * SKH + kb) * 2u);
                mma_f16(s[2*p],   qf[ks][0], qf[ks][1], qf[ks][2], qf[ks][3], bk[0], bk[1]);
                mma_f16(s[2*p+1], qf[ks][0], qf[ks][1], qf[ks][2], qf[ks][3], bk[2], bk[3]);
            }
        }

        float rmax0 = -1e30f, rmax1 = -1e30f;
        if (k0 + 63 <= wmin) {
            #pragma unroll
            for (int nf = 0; nf < 8; nf++) {
                int kj = k0 + nf * 8 + 2 * lt;
                s[nf][0] += slope * (float)(kj - r0);
                s[nf][1] += slope * (float)(kj + 1 - r0);
                s[nf][2] += slope * (float)(kj - (r0 + 8));
                s[nf][3] += slope * (float)(kj + 1 - (r0 + 8));
                rmax0 = fmaxf(rmax0, fmaxf(s[nf][0], s[nf][1]));
                rmax1 = fmaxf(rmax1, fmaxf(s[nf][2], s[nf][3]));
            }
        } else {
            #pragma unroll
            for (int nf = 0; nf < 8; nf++) {
                int kj = k0 + nf * 8 + 2 * lt;
                int d00 = kj - r0, d01 = kj + 1 - r0;
                int d10 = kj - (r0 + 8), d11 = kj + 1 - (r0 + 8);
                s[nf][0] = (d00 <= 0) ? s[nf][0] + slope * (float)d00 : -1e30f;
                s[nf][1] = (d01 <= 0) ? s[nf][1] + slope * (float)d01 : -1e30f;
                s[nf][2] = (d10 <= 0) ? s[nf][2] + slope * (float)d10 : -1e30f;
                s[nf][3] = (d11 <= 0) ? s[nf][3] + slope * (float)d11 : -1e30f;
                rmax0 = fmaxf(rmax0, fmaxf(s[nf][0], s[nf][1]));
                rmax1 = fmaxf(rmax1, fmaxf(s[nf][2], s[nf][3]));
            }
        }
        rmax0 = fmaxf(rmax0, __shfl_xor_sync(0xffffffffu, rmax0, 1));
        rmax0 = fmaxf(rmax0, __shfl_xor_sync(0xffffffffu, rmax0, 2));
        rmax1 = fmaxf(rmax1, __shfl_xor_sync(0xffffffffu, rmax1, 1));
        rmax1 = fmaxf(rmax1, __shfl_xor_sync(0xffffffffu, rmax1, 2));

        float mn0 = fmaxf(m0, rmax0), mn1 = fmaxf(m1, rmax1);
        float c0 = ex2f(m0 - mn0),  c1 = ex2f(m1 - mn1);
        m0 = mn0; m1 = mn1;

        float rs0 = 0.f, rs1 = 0.f;
        #pragma unroll
        for (int nf = 0; nf < 8; nf++) {
            float p0 = ex2f(s[nf][0] - mn0);
            float p1 = ex2f(s[nf][1] - mn0);
            float p2 = ex2f(s[nf][2] - mn1);
            float p3 = ex2f(s[nf][3] - mn1);
            rs0 += p0 + p1;
            rs1 += p2 + p3;
            int swz = nf ^ lg;
            int c = (swz << 3) + 2 * lt;
            *(uint32_t*)&Pw[(lg << 6) + c]        = pack_h2(p0, p1);
            *(uint32_t*)&Pw[((lg + 8) << 6) + c]  = pack_h2(p2, p3);
        }
        lp0 = lp0 * c0 + rs0;
        lp1 = lp1 * c1 + rs1;

        #pragma unroll
        for (int nf = 0; nf < 8; nf++) {
            oacc[nf][0] *= c0; oacc[nf][1] *= c0;
            oacc[nf][2] *= c1; oacc[nf][3] *= c1;
        }

        __syncwarp();

        #pragma unroll
        for (int ks = 0; ks < 4; ks++) {
            int kb = ks * 16;
            int pchunk = (2 * ks + (ah8 >> 3)) ^ (arow & 7);
            uint32_t a[4];
            ldsm4(a, pw_u32 + (uint32_t)((arow << 6) + (pchunk << 3)) * 2u);
            #pragma unroll
            for (int p = 0; p < 4; p++) {
                uint32_t bv[4];
                ldsm4t(bv, vaddr + (uint32_t)(kb * SKH + p * 16) * 2u);
                mma_f16(oacc[2*p],   a[0], a[1], a[2], a[3], bv[0], bv[1]);
                mma_f16(oacc[2*p+1], a[0], a[1], a[2], a[3], bv[2], bv[3]);
            }
        }
    }

    lp0 += __shfl_xor_sync(0xffffffffu, lp0, 1);
    lp0 += __shfl_xor_sync(0xffffffffu, lp0, 2);
    lp1 += __shfl_xor_sync(0xffffffffu, lp1, 1);
    lp1 += __shfl_xor_sync(0xffffffffu, lp1, 2);
    float inv0 = 1.f / lp0, inv1 = 1.f / lp1;
    __half* o0 = &g_oh[(size_t)(b * T_ + r0) * C_ + h * D_];
    __half* o1 = o0 + 8 * C_;
    #pragma unroll
    for (int nf = 0; nf < 8; nf++) {
        int c = nf * 8 + 2 * lt;
        *(uint32_t*)&o0[c] = pack_h2(oacc[nf][0] * inv0, oacc[nf][1] * inv0);
        *(uint32_t*)&o1[c] = pack_h2(oacc[nf][2] * inv1, oacc[nf][3] * inv1);
    }
}

// ---------------------------------------------------------------------------
extern "C" void kernel_launch(void* const* d_in, const int* in_sizes, int n_in,
                              void* d_out, int out_size)
{
    const float* x  = (const float*)d_in[0];
    const float* Wq = (const float*)d_in[1];
    const float* bq = (const float*)d_in[2];
    const float* Wk = (const float*)d_in[3];
    const float* bk = (const float*)d_in[4];
    const float* Wv = (const float*)d_in[5];
    const float* bv = (const float*)d_in[6];
    const float* Wo = (const float*)d_in[7];
    const float* bo = (const float*)d_in[8];
    float* out = (float*)d_out;

    cudaFuncSetAttribute(qkv_gemm_kernel,
                         cudaFuncAttributeMaxDynamicSharedMemorySize, GEMM_SMEM);
    cudaFuncSetAttribute(out_gemm_kernel,
                         cudaFuncAttributeMaxDynamicSharedMemorySize, GEMM_SMEM);
    cudaFuncSetAttribute(attn_mma_kernel,
                         cudaFuncAttributeMaxDynamicSharedMemorySize, ATT_SMEM);

    conv_all_kernel<<<2048, 256>>>(x, Wq, Wk, Wv, Wo);

    qkv_gemm_kernel<<<dim3(24, 64), 128, GEMM_SMEM>>>(bq, bk, bv);

    attn_mma_kernel<<<dim3(T_ / 64, H_, B_), 128, ATT_SMEM>>>();

    out_gemm_kernel<<<dim3(8, 64), 128, GEMM_SMEM>>>(bo, out);
}